// round 16
// baseline (speedup 1.0000x reference)
#include <cuda_runtime.h>
#include <cuda_fp16.h>
#include <cstdint>

#define BATCH    8
#define GH       64
#define C0       64
#define NPTS     16384
#define NFREQ    10
#define HID      256
#define TILE_M   64
#define THREADS  256
#define HSH      288                 // halves per h row (144 words == 16 mod 32)
#define WT_L     65536               // halves per layer (no pads)

// ---------------- device scratch (static, allocation-free) ----------------
__device__ float  g_gamma[BATCH * HID];
__device__ float  g_beta [BATCH * HID];
__device__ __half g_WTb  [BATCH * 4 * WT_L]; // per-batch gamma-baked fp16 weights
__device__ float  g_lvl1 [BATCH * 32 * 32 * C0];
__device__ float  g_lvl2 [BATCH * 16 * 16 * C0];

// ---------------- helpers ----------------
__device__ __forceinline__ float tanh_fast(float y) {     // accurate (output stage)
    float e; asm("ex2.approx.f32 %0, %1;" : "=f"(e) : "f"(y * 2.8853900817779268f));
    float r; asm("rcp.approx.f32 %0, %1;" : "=f"(r) : "f"(e + 1.0f));
    return 1.0f - 2.0f * r;
}
__device__ __forceinline__ float tanh_hw(float x) {       // 1-MUFU approx (hidden layers)
    float r; asm("tanh.approx.f32 %0, %1;" : "=f"(r) : "f"(x)); return r;
}
__device__ __forceinline__ float gelu_f(float x) {
    float u = 0.7978845608028654f * fmaf(0.044715f * x, x * x, x);
    return 0.5f * x * (1.0f + tanh_hw(u));
}
__device__ __forceinline__ void mma_f16(float* d, const uint32_t* a,
                                        uint32_t b0, uint32_t b1) {
    asm volatile(
        "mma.sync.aligned.m16n8k16.row.col.f32.f16.f16.f32 "
        "{%0,%1,%2,%3}, {%4,%5,%6,%7}, {%8,%9}, {%0,%1,%2,%3};"
        : "+f"(d[0]), "+f"(d[1]), "+f"(d[2]), "+f"(d[3])
        : "r"(a[0]), "r"(a[1]), "r"(a[2]), "r"(a[3]), "r"(b0), "r"(b1));
}
// chunk-contiguous k-permutation: within each 32-block, thread cq=(k&7)>>1 owns
// 8 contiguous halves: pos = cq*8 + s*4 + b1*2 + b0  (s=k bit4, b1=k bit3, b0=k bit0)
__device__ __host__ __forceinline__ int posf(int k) {
    return (k & ~31) | (((k >> 1) & 3) << 3) | (((k >> 4) & 1) << 2)
         | (((k >> 3) & 1) << 1) | (k & 1);
}

// ================== merged prep (one launch) ==================
// blocks [0,2048): resize lvl1; [2048,2560): resize lvl2;
// [2560,10752): per-batch gamma-baked weight pack; [10752,10760): FiLM ctx.

template <int HL>
__device__ void resize_body(int bid, int tid, const float* __restrict__ src) {
    int idx = bid * 256 + tid;
    int c = idx & (C0 - 1);
    int v = idx >> 6;
    int x = v % HL;
    int y = (v / HL) % HL;
    int b = v / (HL * HL);

    const float scale = (float)(GH / HL);
    const int   T     = 2 * (GH / HL);

    float sy = (y + 0.5f) * scale - 0.5f;
    float sx = (x + 0.5f) * scale - 0.5f;
    int s0y = (int)floorf(sy - scale) + 1;
    int s0x = (int)floorf(sx - scale) + 1;

    float wy[8], wx[8];
    float sumy = 0.f, sumx = 0.f;
#pragma unroll
    for (int t = 0; t < T; t++) {
        int s = s0y + t;
        float w = 1.0f - fabsf((float)s - sy) / scale;
        w = (s >= 0 && s < GH && w > 0.f) ? w : 0.f;
        wy[t] = w; sumy += w;
        s = s0x + t;
        w = 1.0f - fabsf((float)s - sx) / scale;
        w = (s >= 0 && s < GH && w > 0.f) ? w : 0.f;
        wx[t] = w; sumx += w;
    }
    float inv = 1.0f / (sumy * sumx);

    float acc = 0.f;
#pragma unroll
    for (int a = 0; a < T; a++) {
        if (wy[a] == 0.f) continue;
        const float* row = src + ((((b * GH) + (s0y + a)) * GH) << 6) + c;
        float pacc = 0.f;
#pragma unroll
        for (int t = 0; t < T; t++) {
            if (wx[t] == 0.f) continue;
            pacc += wx[t] * row[(s0x + t) << 6];
        }
        acc += wy[a] * pacc;
    }
    float* dst = (HL == 32) ? g_lvl1 : g_lvl2;
    dst[idx] = acc * inv;
}

// Per-batch gamma-baked weight pack. bid in [0, 8192):
//   bb = bid >> 10; within-batch idx = [l:2][c:3][nw:2][s:1][j:2][lane:5][u:3]
//   value = W[k][n] * gamma[bb][n] (fp16-rounded), with
//   k = c*32 + s*16 + 2*cq + (u&1) + (((u>>1)&1)<<3),
//   n = nw*64 + (2*j + (u>>2))*8 + r    (lane = r*4 + cq)
// Each 256-thread block needs only 16 gammas (n in [nbase, nbase+16)),
// computed cooperatively in smem (64-FMA dot each).
// layer-0 K remap: [0..41]->rows 0..41, [42..43] zero, [44..235]->rows 42..233,
// [236..255] zero (matches the h-tile posf layout).
__device__ void prep_wt_body(int bid, int tid, float* sgam,
                             const float* __restrict__ cv,
                             const float* __restrict__ Wc,
                             const float* __restrict__ bc,
                             const float* __restrict__ W0,
                             const float* __restrict__ W1,
                             const float* __restrict__ W2,
                             const float* __restrict__ W3) {
    int bb  = bid >> 10;
    int idx = (bid & 1023) * 256 + tid;        // within-batch, 2^18 total
    int u    = idx & 7;
    int lane = (idx >> 3) & 31;
    int j    = (idx >> 8) & 3;
    int s    = (idx >> 10) & 1;
    int nw   = (idx >> 11) & 3;
    int c    = (idx >> 13) & 7;
    int l    = idx >> 16;
    int r = lane >> 2, cq = lane & 3;
    int nbase = nw * 64 + j * 16;

    if (tid < 16) {
        int n = nbase + tid;
        float g = bc[n];
#pragma unroll 8
        for (int k2 = 0; k2 < C0; k2++)
            g += cv[bb * C0 + k2] * Wc[k2 * 2 * HID + n];
        sgam[tid] = g + 1.0f;
    }
    __syncthreads();

    int k = c * 32 + s * 16 + 2 * cq + (u & 1) + (((u >> 1) & 1) << 3);
    int n = nbase + (u >> 2) * 8 + r;
    float v = 0.0f;
    if (l == 0) {
        if (k < 42)                  v = W0[k * HID + n];
        else if (k >= 44 && k < 236) v = W0[(k - 2) * HID + n];
    } else if (l == 1) v = W1[k * HID + n];
    else if (l == 2)   v = W2[k * HID + n];
    else               v = W3[k * HID + n];
    v *= sgam[(u >> 2) * 8 + r];
    g_WTb[(size_t)bb * (4 * WT_L) + idx] = __float2half_rn(v);
}

__device__ void prep_ctx_body(int b, int c,
                              const float* __restrict__ cv,
                              const float* __restrict__ Wc,
                              const float* __restrict__ bc) {
    float g  = bc[c];
    float bt = bc[HID + c];
#pragma unroll 8
    for (int k = 0; k < C0; k++) {
        float v = cv[b * C0 + k];
        g  += v * Wc[k * 2 * HID + c];
        bt += v * Wc[k * 2 * HID + HID + c];
    }
    g_gamma[b * HID + c] = g + 1.0f;
    g_beta [b * HID + c] = bt;
}

__global__ void prep_all_kernel(const float* __restrict__ fg,
                                const float* __restrict__ cv,
                                const float* __restrict__ Wc,
                                const float* __restrict__ bc,
                                const float* __restrict__ W0,
                                const float* __restrict__ W1,
                                const float* __restrict__ W2,
                                const float* __restrict__ W3) {
    __shared__ float sgam[16];
    int bid = blockIdx.x, tid = threadIdx.x;
    if (bid < 2048)        resize_body<32>(bid, tid, fg);
    else if (bid < 2560)   resize_body<16>(bid - 2048, tid, fg);
    else if (bid < 10752)  prep_wt_body(bid - 2560, tid, sgam,
                                        cv, Wc, bc, W0, W1, W2, W3);
    else                   prep_ctx_body(bid - 10752, tid, cv, Wc, bc);
}

// ---------------- main fused decoder (fp16 HMMA, gamma-baked weights) ------
__global__ __launch_bounds__(THREADS, 2)
void decoder_kernel(const float* __restrict__ fg,
                    const float* __restrict__ coords,
                    const float* __restrict__ b0, const float* __restrict__ b1,
                    const float* __restrict__ b2, const float* __restrict__ b3,
                    const float* __restrict__ Wout, const float* __restrict__ bout,
                    float* __restrict__ out) {
    extern __shared__ char smem_raw[];
    __half* h_s    = (__half*)smem_raw;                       // 64 * 288
    float*  bias_s = (float*)(h_s + TILE_M * HSH);            // 4*256 (baked: b*g+beta)
    float*  wop_s  = bias_s + 4 * HID;                        // 128*8 (Wout pair-packed)
    float*  bo_s   = wop_s + 128 * 8;                         // 4
    float*  red_s  = bo_s + 4;                                // 64*4*3

    const int tid  = threadIdx.x;
    const int lane = tid & 31;
    const int wid  = tid >> 5;
    const int mw   = wid & 1,  nw = wid >> 1;
    const int m0   = mw * 32,  n0 = nw * 64;
    const int r    = lane >> 2, cq = lane & 3;
    const int b    = blockIdx.x >> 8;
    const int n0p  = (blockIdx.x & 255) * TILE_M;

    const __half* WTb = g_WTb + (size_t)b * (4 * WT_L);
    const int woff = nw * 2048;          // halves within a chunk block

    // B register double buffer; prologue: load (layer0, chunk0, s0) early
    uint4 Bb[2][4];
    {
        const uint4* p = (const uint4*)(WTb + woff) + lane;
        Bb[0][0] = p[0]; Bb[0][1] = p[32]; Bb[0][2] = p[64]; Bb[0][3] = p[96];
    }

    // stage per-CTA params: baked bias' = b_l*gamma + beta
    {
        float gam = g_gamma[b * HID + tid];
        float bet = g_beta [b * HID + tid];
        bias_s[tid]           = fmaf(b0[tid], gam, bet);
        bias_s[HID + tid]     = fmaf(b1[tid], gam, bet);
        bias_s[2 * HID + tid] = fmaf(b2[tid], gam, bet);
        bias_s[3 * HID + tid] = fmaf(b3[tid], gam, bet);
    }
    // Wout pair-packed: wop_s[(n>>1)*8 + t] = Wout[(n>>1)*6 + t] (t<6), pad t=6,7
    for (int jj = tid; jj < 128 * 8; jj += THREADS) {
        int pair = jj >> 3, t = jj & 7;
        wop_s[jj] = (t < 6) ? Wout[pair * 6 + t] : 0.0f;
    }
    if (tid < 3) bo_s[tid] = bout[tid];

    // ---- build features (fp16, posf-permuted k): 4 threads per point ----
    {
        int p = tid >> 2, q = tid & 3;
        float cy = coords[(n0p + p) * 2 + 0];
        float cx = coords[(n0p + p) * 2 + 1];
        __half* hp = h_s + p * HSH;

        if (q < 2) {
            // posenc via exact double-angle recurrence: one sincosf per chain.
            float coord = (q == 0) ? cy : cx;
            float sv, cvv;
            sincosf(coord * 3.14159265358979323846f, &sv, &cvv);
#pragma unroll
            for (int f = 0; f < NFREQ; f++) {
                hp[posf(2 + 4 * f + q)]     = __float2half_rn(sv);
                hp[posf(2 + 4 * f + 2 + q)] = __float2half_rn(cvv);
                float ns = 2.0f * sv * cvv;
                float nc = 1.0f - 2.0f * sv * sv;
                sv = ns; cvv = nc;
            }
        } else if (q == 2) {
            hp[posf(0)] = __float2half_rn(cy);
            hp[posf(1)] = __float2half_rn(cx);
            hp[posf(42)] = __float2half_rn(0.f);
            hp[posf(43)] = __float2half_rn(0.f);
#pragma unroll
            for (int k = 236; k < 246; k++) hp[posf(k)] = __float2half_rn(0.f);
        } else {
#pragma unroll
            for (int k = 246; k < 256; k++) hp[posf(k)] = __float2half_rn(0.f);
        }

#pragma unroll
        for (int lvl = 0; lvl < 3; lvl++) {
            int Hl = GH >> lvl;
            const float* G = (lvl == 0) ? fg : ((lvl == 1) ? g_lvl1 : g_lvl2);
            float yf = (cy + 1.0f) * 0.5f * (float)(Hl - 1);
            float xf = (cx + 1.0f) * 0.5f * (float)(Hl - 1);
            float y0f = floorf(yf), x0f = floorf(xf);
            float wy = yf - y0f, wx = xf - x0f;
            int y0 = min(max((int)y0f, 0), Hl - 1);
            int x0 = min(max((int)x0f, 0), Hl - 1);
            int y1 = min(y0 + 1, Hl - 1);
            int x1 = min(x0 + 1, Hl - 1);
            const float* p00 = G + ((((b * Hl) + y0) * Hl + x0) << 6);
            const float* p01 = G + ((((b * Hl) + y0) * Hl + x1) << 6);
            const float* p10 = G + ((((b * Hl) + y1) * Hl + x0) << 6);
            const float* p11 = G + ((((b * Hl) + y1) * Hl + x1) << 6);
            float omx = 1.0f - wx, omy = 1.0f - wy;
            int base = 44 + lvl * 64 + q * 16;
#pragma unroll
            for (int cc = 0; cc < 4; cc++) {
                int c = q * 16 + cc * 4;
                float4 v00 = *(const float4*)(p00 + c);
                float4 v01 = *(const float4*)(p01 + c);
                float4 v10 = *(const float4*)(p10 + c);
                float4 v11 = *(const float4*)(p11 + c);
                float f0 = (v00.x * omx + v01.x * wx) * omy + (v10.x * omx + v11.x * wx) * wy;
                float f1 = (v00.y * omx + v01.y * wx) * omy + (v10.y * omx + v11.y * wx) * wy;
                float f2 = (v00.z * omx + v01.z * wx) * omy + (v10.z * omx + v11.z * wx) * wy;
                float f3 = (v00.w * omx + v01.w * wx) * omy + (v10.w * omx + v11.w * wx) * wy;
                int pp = posf(base + cc * 4);
                *(__half2*)(hp + pp)     = __floats2half2_rn(f0, f1);
                *(__half2*)(hp + pp + 8) = __floats2half2_rn(f2, f3);
            }
        }
    }
    __syncthreads();    // h tile + params visible to all warps

    // ---- 4 FiLM'd MLP layers on tensor cores (fp16 m16n8k16) ----
    for (int l = 0; l < 4; l++) {
        const __half* WTl = WTb + l * WT_L;

        float acc[2][8][4];
#pragma unroll
        for (int i = 0; i < 2; i++)
#pragma unroll
            for (int j = 0; j < 8; j++)
#pragma unroll
                for (int v = 0; v < 4; v++) acc[i][j][v] = 0.f;

#pragma unroll
        for (int c = 0; c < 8; c++) {
            // A: one LDS.128 per (mt,row-half) covers the whole 32-k chunk
            uint32_t a[2][2][4];     // [s][mt][frag]
#pragma unroll
            for (int mt = 0; mt < 2; mt++) {
                int row = m0 + mt * 16 + r;
                const char* h0 = (const char*)(h_s + row * HSH) + c * 64 + cq * 16;
                const char* h1 = (const char*)(h_s + (row + 8) * HSH) + c * 64 + cq * 16;
                uint4 A0 = *(const uint4*)h0;
                uint4 A1 = *(const uint4*)h1;
                a[0][mt][0] = A0.x; a[0][mt][1] = A1.x;
                a[0][mt][2] = A0.y; a[0][mt][3] = A1.y;
                a[1][mt][0] = A0.z; a[1][mt][1] = A1.z;
                a[1][mt][2] = A0.w; a[1][mt][3] = A1.w;
            }
#pragma unroll
            for (int s = 0; s < 2; s++) {
                const int step = c * 2 + s;
                const int cur  = step & 1;
                if (step < 15) {
                    int ns = step + 1;
                    const uint4* np = (const uint4*)(WTl + (ns >> 1) * 8192 +
                                                     (ns & 1) * 1024 + woff) + lane;
                    Bb[cur ^ 1][0] = np[0];  Bb[cur ^ 1][1] = np[32];
                    Bb[cur ^ 1][2] = np[64]; Bb[cur ^ 1][3] = np[96];
                } else if (l < 3) {
                    const uint4* np = (const uint4*)(WTl + WT_L + woff) + lane;
                    Bb[cur ^ 1][0] = np[0];  Bb[cur ^ 1][1] = np[32];
                    Bb[cur ^ 1][2] = np[64]; Bb[cur ^ 1][3] = np[96];
                }
#pragma unroll
                for (int j = 0; j < 4; j++) {
                    uint4 B = Bb[cur][j];
                    mma_f16(acc[0][2 * j],     a[s][0], B.x, B.y);
                    mma_f16(acc[1][2 * j],     a[s][1], B.x, B.y);
                    mma_f16(acc[0][2 * j + 1], a[s][0], B.z, B.w);
                    mma_f16(acc[1][2 * j + 1], a[s][1], B.z, B.w);
                }
            }
        }
        __syncthreads();   // all A-reads of h done before epilogue writes

        if (l < 3) {
            // ---- epilogue: baked bias + gelu -> fp16, write back permuted ----
#pragma unroll
            for (int nt = 0; nt < 8; nt++) {
                int n  = n0 + nt * 8 + 2 * cq;
                int pp = (n & ~31) | (cq << 3) | (((n >> 4) & 1) << 2)
                       | (((n >> 3) & 1) << 1);
                float2 bi = *(const float2*)(bias_s + l * HID + n);
#pragma unroll
                for (int mt = 0; mt < 2; mt++) {
                    int p0 = m0 + mt * 16 + r;
                    *(__half2*)(h_s + p0 * HSH + pp) = __floats2half2_rn(
                        gelu_f(acc[mt][nt][0] + bi.x),
                        gelu_f(acc[mt][nt][1] + bi.y));
                    *(__half2*)(h_s + (p0 + 8) * HSH + pp) = __floats2half2_rn(
                        gelu_f(acc[mt][nt][2] + bi.x),
                        gelu_f(acc[mt][nt][3] + bi.y));
                }
            }
            __syncthreads();
        } else {
            // ---- fused output head: gelu in regs -> xWout -> reduce ----
            float po[12];
#pragma unroll
            for (int i = 0; i < 12; i++) po[i] = 0.f;
#pragma unroll
            for (int nt = 0; nt < 8; nt++) {
                int n  = n0 + nt * 8 + 2 * cq;
                float2 bi = *(const float2*)(bias_s + 3 * HID + n);
                const float* wp = wop_s + (n >> 1) * 8;
                float4 wA = *(const float4*)wp;          // w00 w01 w02 w10
                float2 wB = *(const float2*)(wp + 4);    // w11 w12
#pragma unroll
                for (int mt = 0; mt < 2; mt++) {
                    float ga = gelu_f(acc[mt][nt][0] + bi.x);
                    float gb = gelu_f(acc[mt][nt][1] + bi.y);
                    float gc = gelu_f(acc[mt][nt][2] + bi.x);
                    float gd = gelu_f(acc[mt][nt][3] + bi.y);
                    int ix = mt * 6;
                    po[ix + 0] += ga * wA.x + gb * wA.w;
                    po[ix + 1] += ga * wA.y + gb * wB.x;
                    po[ix + 2] += ga * wA.z + gb * wB.y;
                    po[ix + 3] += gc * wA.x + gd * wA.w;
                    po[ix + 4] += gc * wA.y + gd * wB.x;
                    po[ix + 5] += gc * wA.z + gd * wB.y;
                }
            }
            // reduce across the 4 cq lanes (lane bits 0-1)
#pragma unroll
            for (int i = 0; i < 12; i++) {
                po[i] += __shfl_xor_sync(0xffffffffu, po[i], 1);
                po[i] += __shfl_xor_sync(0xffffffffu, po[i], 2);
            }
            if (cq == 0) {
#pragma unroll
                for (int mt = 0; mt < 2; mt++)
#pragma unroll
                    for (int hh = 0; hh < 2; hh++) {
                        int p = m0 + mt * 16 + hh * 8 + r;
                        float* dst = red_s + (p * 4 + nw) * 3;
                        dst[0] = po[mt * 6 + hh * 3 + 0];
                        dst[1] = po[mt * 6 + hh * 3 + 1];
                        dst[2] = po[mt * 6 + hh * 3 + 2];
                    }
            }
            __syncthreads();
            if (tid < 192) {
                int p = tid & 63, o = tid >> 6;
                const float* q4 = red_s + p * 12 + o;
                float acc2 = bo_s[o] + (q4[0] + q4[3]) + (q4[6] + q4[9]);
                out[((size_t)b * NPTS + n0p + p) * 3 + o] = tanh_fast(acc2);
            }
        }
    }
}

// ---------------- launch ----------------
extern "C" void kernel_launch(void* const* d_in, const int* in_sizes, int n_in,
                              void* d_out, int out_size) {
    const float* fg = (const float*)d_in[0];
    const float* cv = (const float*)d_in[1];
    const float* co = (const float*)d_in[2];
    const float* Wc = (const float*)d_in[3];
    const float* bc = (const float*)d_in[4];
    const float* W0 = (const float*)d_in[5];
    const float* b0 = (const float*)d_in[6];
    const float* W1 = (const float*)d_in[7];
    const float* b1 = (const float*)d_in[8];
    const float* W2 = (const float*)d_in[9];
    const float* b2 = (const float*)d_in[10];
    const float* W3 = (const float*)d_in[11];
    const float* b3 = (const float*)d_in[12];
    const float* Wo = (const float*)d_in[13];
    const float* bo = (const float*)d_in[14];
    float* out = (float*)d_out;

    const int smemB = TILE_M * HSH * 2 +
                      (4 * HID + 128 * 8 + 4 + 64 * 12) * 4;
    cudaFuncSetAttribute(decoder_kernel,
                         cudaFuncAttributeMaxDynamicSharedMemorySize, smemB);

    prep_all_kernel<<<10760, 256>>>(fg, cv, Wc, bc, W0, W1, W2, W3);
    decoder_kernel<<<BATCH * (NPTS / TILE_M), THREADS, smemB>>>(
        fg, co, b0, b1, b2, b3, Wo, bo, out);
}